// round 12
// baseline (speedup 1.0000x reference)
#include <cuda_runtime.h>
#include <cstdint>

#define NCOLS 8192
#define NROWS 8192
#define ROWS_PER_CTA 2
#define THREADS 512
#define NWARP (THREADS / 32)

__global__ __launch_bounds__(THREADS) void a4_quant_kernel(
    const float* __restrict__ x, const int* __restrict__ perm,
    float* __restrict__ out)
{
    extern __shared__ float srow[];  // ROWS_PER_CTA * NCOLS floats = 64 KB
    const size_t row0 = (size_t)blockIdx.x * ROWS_PER_CTA;

    // ---- Permutation dtype sniff (warp-uniform, L1/L2-hot) ----
    // As int32 words: an int64 perm (values < 8192) has all-zero odd words;
    // an int32 perm has at most one zero among any 64 odd words.
    const int lane = threadIdx.x & 31;
    const int hiw = perm[2 * lane + 1] | perm[2 * lane + 65];
    const bool is64 = (__ballot_sync(0xffffffffu, hiw != 0) == 0u);

    // ---- Stage ROWS_PER_CTA rows into SMEM via cp.async ----
    {
        const char* src = (const char*)(x + row0 * NCOLS);
        unsigned s = (unsigned)__cvta_generic_to_shared(srow);
        #pragma unroll
        for (int i = threadIdx.x; i < ROWS_PER_CTA * NCOLS / 4; i += THREADS) {
            asm volatile("cp.async.cg.shared.global [%0], [%1], 16;\n"
                         :: "r"(s + i * 16), "l"(src + (size_t)i * 16));
        }
        asm volatile("cp.async.commit_group;\n"
                     "cp.async.wait_group 0;\n" ::: "memory");
    }
    __syncthreads();

    const int warp = threadIdx.x >> 5;
    const int kblk = lane >> 3;   // which of the warp's 4 blocks this lane serves
    const int g    = lane & 7;    // lane within the 8-lane block group

    // Index loader for one 128-column span (4 quant blocks of 32; lanes
    // 8k..8k+7 own block k; lane handles 4 consecutive columns).
    auto load_idx = [&](int s) -> int4 {
        const int col0 = (s * 4 + kblk) * 32 + g * 4;
        if (is64) {
            const int4 a = *(const int4*)(perm + 2 * col0);
            const int4 b = *(const int4*)(perm + 2 * col0 + 4);
            return make_int4(a.x, a.z, b.x, b.z);   // low words of 4 int64s
        }
        return *(const int4*)(perm + col0);
    };

    // Quantize 4 values of one block-row given their raw bits + block amax.
    auto quant4 = [&](unsigned b0, unsigned b1, unsigned b2, unsigned b3,
                      unsigned um) -> uint4 {
        // Clamp amax exponent so threshold arithmetic never underflows
        // (only reachable for amax < 2^-122; abs err < 2^-122).
        const unsigned m2   = max(um, 0x02800000u);
        const unsigned mexp = m2 & 0x7f800000u;      // 2^E bits
        const unsigned six  = mexp | 0x00400000u;    // 6   * 2^(E-2)
        const unsigned one  = mexp - 0x01000000u;    // 1   * 2^(E-2)
        const unsigned half = mexp - 0x01800000u;    // 0.5 * 2^(E-2)
        const unsigned t075 = half | 0x00400000u;    // 0.75* 2^(E-2)
        const unsigned t025 = mexp - 0x02000000u;    // 0.25* 2^(E-2)

        // FP4 E2M1 quantization in output scale, ties round UP
        // (matches searchsorted(FP4_MID, mag, side="right")).
        uint4 qv;
        {
            const unsigned u = b0 & 0x7fffffffu;
            const unsigned r = (min(u, six) + 0x00200000u) & 0xffc00000u;
            const unsigned q = (u >= one) ? r
                             : (u >= t075) ? one
                             : (u >= t025) ? half : 0u;
            qv.x = q | (b0 & 0x80000000u);
        }
        {
            const unsigned u = b1 & 0x7fffffffu;
            const unsigned r = (min(u, six) + 0x00200000u) & 0xffc00000u;
            const unsigned q = (u >= one) ? r
                             : (u >= t075) ? one
                             : (u >= t025) ? half : 0u;
            qv.y = q | (b1 & 0x80000000u);
        }
        {
            const unsigned u = b2 & 0x7fffffffu;
            const unsigned r = (min(u, six) + 0x00200000u) & 0xffc00000u;
            const unsigned q = (u >= one) ? r
                             : (u >= t075) ? one
                             : (u >= t025) ? half : 0u;
            qv.z = q | (b2 & 0x80000000u);
        }
        {
            const unsigned u = b3 & 0x7fffffffu;
            const unsigned r = (min(u, six) + 0x00200000u) & 0xffc00000u;
            const unsigned q = (u >= one) ? r
                             : (u >= t075) ? one
                             : (u >= t025) ? half : 0u;
            qv.w = q | (b3 & 0x80000000u);
        }
        return qv;
    };

    // 8-lane butterfly amax reduce (uint max == float max on abs bits).
    auto amax8 = [&](unsigned u0, unsigned u1, unsigned u2, unsigned u3)
        -> unsigned {
        unsigned um = max(max(u0 & 0x7fffffffu, u1 & 0x7fffffffu),
                          max(u2 & 0x7fffffffu, u3 & 0x7fffffffu));
        um = max(um, __shfl_xor_sync(0xffffffffu, um, 1));
        um = max(um, __shfl_xor_sync(0xffffffffu, um, 2));
        um = max(um, __shfl_xor_sync(0xffffffffu, um, 4));
        return um;
    };

    // Each warp owns 4 spans: s = warp + {0,1,2,3}*NWARP. Process as 2 pairs,
    // issuing ALL 16 gather LDS of a pair before any dependent math so the
    // second span's gather latency hides under the first span's alu work.
    #pragma unroll
    for (int p = 0; p < 2; ++p) {
        const int sA = warp + (2 * p)     * NWARP;
        const int sB = warp + (2 * p + 1) * NWARP;
        const int colA = (sA * 4 + kblk) * 32 + g * 4;
        const int colB = (sB * 4 + kblk) * 32 + g * 4;

        const int4 cA = load_idx(sA);
        const int4 cB = load_idx(sB);

        // 16 independent LDS.32 gathers (2 spans x 2 rows x 4 cols)
        const float* r0 = srow;
        const float* r1 = srow + NCOLS;
        const unsigned a00 = __float_as_uint(r0[cA.x]);
        const unsigned a01 = __float_as_uint(r0[cA.y]);
        const unsigned a02 = __float_as_uint(r0[cA.z]);
        const unsigned a03 = __float_as_uint(r0[cA.w]);
        const unsigned a10 = __float_as_uint(r1[cA.x]);
        const unsigned a11 = __float_as_uint(r1[cA.y]);
        const unsigned a12 = __float_as_uint(r1[cA.z]);
        const unsigned a13 = __float_as_uint(r1[cA.w]);
        const unsigned b00 = __float_as_uint(r0[cB.x]);
        const unsigned b01 = __float_as_uint(r0[cB.y]);
        const unsigned b02 = __float_as_uint(r0[cB.z]);
        const unsigned b03 = __float_as_uint(r0[cB.w]);
        const unsigned b10 = __float_as_uint(r1[cB.x]);
        const unsigned b11 = __float_as_uint(r1[cB.y]);
        const unsigned b12 = __float_as_uint(r1[cB.z]);
        const unsigned b13 = __float_as_uint(r1[cB.w]);

        const unsigned mA0 = amax8(a00, a01, a02, a03);
        const unsigned mA1 = amax8(a10, a11, a12, a13);
        const unsigned mB0 = amax8(b00, b01, b02, b03);
        const unsigned mB1 = amax8(b10, b11, b12, b13);

        *(uint4*)(out +  row0      * NCOLS + colA) = quant4(a00, a01, a02, a03, mA0);
        *(uint4*)(out + (row0 + 1) * NCOLS + colA) = quant4(a10, a11, a12, a13, mA1);
        *(uint4*)(out +  row0      * NCOLS + colB) = quant4(b00, b01, b02, b03, mB0);
        *(uint4*)(out + (row0 + 1) * NCOLS + colB) = quant4(b10, b11, b12, b13, mB1);
    }
}

extern "C" void kernel_launch(void* const* d_in, const int* in_sizes, int n_in,
                              void* d_out, int out_size)
{
    // Identify inputs by element count (x: 8192*8192, permutation: 8192)
    const float* x     = nullptr;
    const void*  permb = nullptr;
    if (n_in >= 2 && in_sizes[0] == NCOLS) {
        permb = d_in[0];
        x     = (const float*)d_in[1];
    } else {
        x     = (const float*)d_in[0];
        permb = d_in[1];
    }
    float* out = (float*)d_out;

    const int smem_bytes = ROWS_PER_CTA * NCOLS * (int)sizeof(float);  // 64 KB
    cudaFuncSetAttribute(a4_quant_kernel,
                         cudaFuncAttributeMaxDynamicSharedMemorySize, smem_bytes);
    a4_quant_kernel<<<NROWS / ROWS_PER_CTA, THREADS, smem_bytes>>>(
        x, (const int*)permb, out);
}

// round 15
// speedup vs baseline: 1.0190x; 1.0190x over previous
#include <cuda_runtime.h>
#include <cstdint>

#define NCOLS 8192
#define NROWS 8192
#define THREADS 512
#define NWARP (THREADS / 32)

__global__ __launch_bounds__(THREADS) void a4_quant_kernel(
    const float* __restrict__ x, const int* __restrict__ perm,
    float* __restrict__ out)
{
    extern __shared__ float srow[];  // one row: NCOLS floats = 32 KB
    const size_t row = (size_t)blockIdx.x;

    // ---- Permutation dtype sniff (warp-uniform, L1/L2-hot) ----
    // As int32 words: an int64 perm (values < 8192) has all-zero odd words;
    // an int32 perm has at most one zero among any 64 odd words.
    const int lane = threadIdx.x & 31;
    const int hiw = perm[2 * lane + 1] | perm[2 * lane + 65];
    const bool is64 = (__ballot_sync(0xffffffffu, hiw != 0) == 0u);

    // ---- Stage one row into SMEM via cp.async ----
    {
        const char* src = (const char*)(x + row * NCOLS);
        unsigned s = (unsigned)__cvta_generic_to_shared(srow);
        #pragma unroll
        for (int i = threadIdx.x; i < NCOLS / 4; i += THREADS) {
            asm volatile("cp.async.cg.shared.global [%0], [%1], 16;\n"
                         :: "r"(s + i * 16), "l"(src + (size_t)i * 16));
        }
        asm volatile("cp.async.commit_group;\n"
                     "cp.async.wait_group 0;\n" ::: "memory");
    }
    __syncthreads();

    const int warp = threadIdx.x >> 5;
    const int kblk = lane >> 3;   // which of the warp's 4 blocks this lane serves
    const int g    = lane & 7;    // lane within the 8-lane block group

    float* orow = out + row * NCOLS;

    // Warp iteration covers a 128-column span = 4 quant blocks of 32.
    // Lanes 8k..8k+7 own block k; lane handles 4 consecutive columns.
    for (int s = warp; s < NCOLS / 128; s += NWARP) {
        const int col0 = (s * 4 + kblk) * 32 + g * 4;

        // Index load straight from the input buffer (L1/L2-hot)
        int4 c4;
        if (is64) {
            const int4 a = *(const int4*)(perm + 2 * col0);
            const int4 b = *(const int4*)(perm + 2 * col0 + 4);
            c4 = make_int4(a.x, a.z, b.x, b.z);   // low words of 4 int64s
        } else {
            c4 = *(const int4*)(perm + col0);
        }

        // Random-bank LDS.32 gather, 4-way ILP
        const unsigned b0 = __float_as_uint(srow[c4.x]);
        const unsigned b1 = __float_as_uint(srow[c4.y]);
        const unsigned b2 = __float_as_uint(srow[c4.z]);
        const unsigned b3 = __float_as_uint(srow[c4.w]);

        const unsigned u0 = b0 & 0x7fffffffu;
        const unsigned u1 = b1 & 0x7fffffffu;
        const unsigned u2 = b2 & 0x7fffffffu;
        const unsigned u3 = b3 & 0x7fffffffu;

        // Block amax (uint max == float max for abs bits): local then
        // 8-lane butterfly reduce.
        unsigned um = max(max(u0, u1), max(u2, u3));
        um = max(um, __shfl_xor_sync(0xffffffffu, um, 1));
        um = max(um, __shfl_xor_sync(0xffffffffu, um, 2));
        um = max(um, __shfl_xor_sync(0xffffffffu, um, 4));

        // Clamp amax exponent so threshold arithmetic never underflows
        // (only reachable for amax < 2^-122; abs err < 2^-122).
        const unsigned m2   = max(um, 0x02800000u);
        const unsigned mexp = m2 & 0x7f800000u;      // 2^E bits
        const unsigned six  = mexp | 0x00400000u;    // 6   * 2^(E-2)
        const unsigned one  = mexp - 0x01000000u;    // 1   * 2^(E-2)
        const unsigned half = mexp - 0x01800000u;    // 0.5 * 2^(E-2)
        const unsigned t075 = half | 0x00400000u;    // 0.75* 2^(E-2)
        const unsigned t025 = mexp - 0x02000000u;    // 0.25* 2^(E-2)

        // FP4 E2M1 quantization in output scale, ties round UP
        // (matches searchsorted(FP4_MID, mag, side="right")).
        uint4 qv;
        {
            const unsigned r = (min(u0, six) + 0x00200000u) & 0xffc00000u;
            const unsigned q = (u0 >= one) ? r
                             : (u0 >= t075) ? one
                             : (u0 >= t025) ? half : 0u;
            qv.x = q | (b0 & 0x80000000u);
        }
        {
            const unsigned r = (min(u1, six) + 0x00200000u) & 0xffc00000u;
            const unsigned q = (u1 >= one) ? r
                             : (u1 >= t075) ? one
                             : (u1 >= t025) ? half : 0u;
            qv.y = q | (b1 & 0x80000000u);
        }
        {
            const unsigned r = (min(u2, six) + 0x00200000u) & 0xffc00000u;
            const unsigned q = (u2 >= one) ? r
                             : (u2 >= t075) ? one
                             : (u2 >= t025) ? half : 0u;
            qv.z = q | (b2 & 0x80000000u);
        }
        {
            const unsigned r = (min(u3, six) + 0x00200000u) & 0xffc00000u;
            const unsigned q = (u3 >= one) ? r
                             : (u3 >= t075) ? one
                             : (u3 >= t025) ? half : 0u;
            qv.w = q | (b3 & 0x80000000u);
        }

        // STG.128 of 4 consecutive output columns
        *(uint4*)(orow + col0) = qv;
    }
}

extern "C" void kernel_launch(void* const* d_in, const int* in_sizes, int n_in,
                              void* d_out, int out_size)
{
    // Identify inputs by element count (x: 8192*8192, permutation: 8192)
    const float* x     = nullptr;
    const void*  permb = nullptr;
    if (n_in >= 2 && in_sizes[0] == NCOLS) {
        permb = d_in[0];
        x     = (const float*)d_in[1];
    } else {
        x     = (const float*)d_in[0];
        permb = d_in[1];
    }
    float* out = (float*)d_out;

    const int smem_bytes = NCOLS * (int)sizeof(float);  // 32 KB
    cudaFuncSetAttribute(a4_quant_kernel,
                         cudaFuncAttributeMaxDynamicSharedMemorySize, smem_bytes);
    a4_quant_kernel<<<NROWS, THREADS, smem_bytes>>>(x, (const int*)permb, out);
}